// round 14
// baseline (speedup 1.0000x reference)
#include <cuda_runtime.h>
#include <cuda_bf16.h>
#include <cstdint>
#include <cstddef>

// Problem constants
#define BB   2
#define NN   1024
#define CC   1024
#define HH   16
#define DH   64
#define MROWS (BB*NN)
#define OUT_ELEMS  (BB*NN*CC)                 // 2,097,152
#define ATTN_ELEMS (BB*NN*NN*HH)              // 33,554,432

// ---------------- scratch ----------------
__device__ float g_mha_q[MROWS * CC];
__device__ float g_mha_kv[MROWS * 2 * CC];
__device__ float g_mha_o[MROWS * CC];
__device__ float g_mha_attn[ATTN_ELEMS];      // [b,h,n,m]

// ---------------- tf32 helpers ----------------
__device__ __forceinline__ uint32_t f2tf(float x) {
    uint32_t r;
    asm("cvt.rna.tf32.f32 %0, %1;" : "=r"(r) : "f"(x));
    return r;
}

#define MMA_TF32(d, a, b) \
    asm volatile("mma.sync.aligned.m16n8k8.row.col.f32.tf32.tf32.f32 " \
        "{%0,%1,%2,%3}, {%4,%5,%6,%7}, {%8,%9}, {%0,%1,%2,%3};" \
        : "+f"((d)[0]), "+f"((d)[1]), "+f"((d)[2]), "+f"((d)[3]) \
        : "r"((a)[0]), "r"((a)[1]), "r"((a)[2]), "r"((a)[3]), \
          "r"((b)[0]), "r"((b)[1]))

// ================= Fused GEMM (+ optional transpose CTAs) =================
// GEMM CTAs (bid < gemm_blocks): C = A @ B^T + bias, 128x128 block, 256 thr,
//   8 warps (2m x 4n), warp tile 64x32, k-tile 16, double-buffered smem.
//   Columns [0,1024) -> C0 ; [1024,...) -> C1 (ldc 2048).
// Transpose CTAs (bid >= gemm_blocks): attn [b,h,n,m] -> [b,n,m,h].
#define GSTR 20
#define GHALF (128 * GSTR)          // words per buffer per operand

__global__ __launch_bounds__(256, 2) void mha_gemm_fused(
    const float* __restrict__ A,
    const float* __restrict__ B0, const float* __restrict__ B1,
    const float* __restrict__ bias0, const float* __restrict__ bias1,
    float* __restrict__ C0, float* __restrict__ C1, int K,
    int ncol, int gemm_blocks,
    const float* __restrict__ tsrc, float* __restrict__ tdst)
{
    __shared__ uint32_t smraw[4 * GHALF];      // 40,960 B

    const int bid = blockIdx.x;
    const int t   = threadIdx.x;

    if (bid >= gemm_blocks) {
        // ---------- transpose path ----------
        float (*tile)[257] = reinterpret_cast<float(*)[257]>(smraw);
        const int tb = bid - gemm_blocks;
        const int mc = tb & 3;
        const int n  = (tb >> 2) & 1023;
        const int b  = tb >> 12;
        const int m0 = mc * 256;

        #pragma unroll
        for (int r = 0; r < 4; r++) {
            int li = r * 256 + t;             // 1024 f4 slots: 16 h x 64 f4
            int hh = li >> 6;
            int mq = (li & 63) << 2;
            float4 v = *(const float4*)(tsrc + ((size_t)((b * HH + hh) * NN + n)) * NN + m0 + mq);
            tile[hh][mq]     = v.x;
            tile[hh][mq + 1] = v.y;
            tile[hh][mq + 2] = v.z;
            tile[hh][mq + 3] = v.w;
        }
        __syncthreads();

        float* dbase = tdst + ((size_t)(b * NN + n) * NN + m0) * HH;
        #pragma unroll
        for (int r = 0; r < 4; r++) {
            int li = r * 256 + t;             // 256 m x 4 h-quads
            int m  = li >> 2;
            int hq = (li & 3) << 2;
            float4 v;
            v.x = tile[hq + 0][m];
            v.y = tile[hq + 1][m];
            v.z = tile[hq + 2][m];
            v.w = tile[hq + 3][m];
            *(float4*)(dbase + (size_t)m * HH + hq) = v;
        }
        return;
    }

    // ---------- GEMM path ----------
    uint32_t* Asm = smraw;                    // [2][GHALF]
    uint32_t* Bsm = smraw + 2 * GHALF;

    const int lane = t & 31;
    const int w    = t >> 5;
    const int bm   = (bid / ncol) * 128;
    const int bn   = (bid % ncol) * 128;
    const int wm   = (w >> 2) * 64;
    const int wn   = (w & 3) * 32;
    const int g    = lane >> 2;
    const int tg   = lane & 3;

    const int lr = t >> 1;
    const int ls = (t & 1) * 8;

    float acc[4][4][4];
    #pragma unroll
    for (int mi = 0; mi < 4; mi++)
        #pragma unroll
        for (int ni = 0; ni < 4; ni++)
            #pragma unroll
            for (int r = 0; r < 4; r++) acc[mi][ni][r] = 0.0f;

    const float* Ap = A + (size_t)(bm + lr) * K;
    const float* Bp;
    {
        int cn = bn + lr;
        Bp = (cn < CC) ? (B0 + (size_t)cn * K)
                       : (B1 + (size_t)(cn - CC) * K);
    }

    float4 la[2], lb[2];
    la[0] = *(const float4*)(Ap + ls);
    la[1] = *(const float4*)(Ap + ls + 4);
    lb[0] = *(const float4*)(Bp + ls);
    lb[1] = *(const float4*)(Bp + ls + 4);

    {
        uint4 sa0, sa1, sb0, sb1;
        sa0.x = f2tf(la[0].x); sa0.y = f2tf(la[0].y); sa0.z = f2tf(la[0].z); sa0.w = f2tf(la[0].w);
        sa1.x = f2tf(la[1].x); sa1.y = f2tf(la[1].y); sa1.z = f2tf(la[1].z); sa1.w = f2tf(la[1].w);
        sb0.x = f2tf(lb[0].x); sb0.y = f2tf(lb[0].y); sb0.z = f2tf(lb[0].z); sb0.w = f2tf(lb[0].w);
        sb1.x = f2tf(lb[1].x); sb1.y = f2tf(lb[1].y); sb1.z = f2tf(lb[1].z); sb1.w = f2tf(lb[1].w);
        *(uint4*)&Asm[lr * GSTR + ls]     = sa0;
        *(uint4*)&Asm[lr * GSTR + ls + 4] = sa1;
        *(uint4*)&Bsm[lr * GSTR + ls]     = sb0;
        *(uint4*)&Bsm[lr * GSTR + ls + 4] = sb1;
    }
    __syncthreads();

    int cur = 0;
    for (int k0 = 16; k0 <= K; k0 += 16) {
        const bool more = (k0 < K);
        if (more) {
            la[0] = *(const float4*)(Ap + k0 + ls);
            la[1] = *(const float4*)(Ap + k0 + ls + 4);
            lb[0] = *(const float4*)(Bp + k0 + ls);
            lb[1] = *(const float4*)(Bp + k0 + ls + 4);
        }

        const uint32_t* Ac = Asm + cur * GHALF;
        const uint32_t* Bc = Bsm + cur * GHALF;
        #pragma unroll
        for (int kk = 0; kk < 16; kk += 8) {
            uint32_t af[4][4], bf[4][2];
            const int c = kk + tg;
            #pragma unroll
            for (int mi = 0; mi < 4; mi++) {
                int r = wm + mi * 16 + g;
                af[mi][0] = Ac[r * GSTR + c];
                af[mi][1] = Ac[(r + 8) * GSTR + c];
                af[mi][2] = Ac[r * GSTR + c + 4];
                af[mi][3] = Ac[(r + 8) * GSTR + c + 4];
            }
            #pragma unroll
            for (int ni = 0; ni < 4; ni++) {
                int r = wn + ni * 8 + g;
                bf[ni][0] = Bc[r * GSTR + c];
                bf[ni][1] = Bc[r * GSTR + c + 4];
            }
            #pragma unroll
            for (int mi = 0; mi < 4; mi++)
                #pragma unroll
                for (int ni = 0; ni < 4; ni++)
                    MMA_TF32(acc[mi][ni], af[mi], bf[ni]);
        }

        if (more) {
            uint32_t* An = Asm + (cur ^ 1) * GHALF;
            uint32_t* Bn = Bsm + (cur ^ 1) * GHALF;
            uint4 sa0, sa1, sb0, sb1;
            sa0.x = f2tf(la[0].x); sa0.y = f2tf(la[0].y); sa0.z = f2tf(la[0].z); sa0.w = f2tf(la[0].w);
            sa1.x = f2tf(la[1].x); sa1.y = f2tf(la[1].y); sa1.z = f2tf(la[1].z); sa1.w = f2tf(la[1].w);
            sb0.x = f2tf(lb[0].x); sb0.y = f2tf(lb[0].y); sb0.z = f2tf(lb[0].z); sb0.w = f2tf(lb[0].w);
            sb1.x = f2tf(lb[1].x); sb1.y = f2tf(lb[1].y); sb1.z = f2tf(lb[1].z); sb1.w = f2tf(lb[1].w);
            *(uint4*)&An[lr * GSTR + ls]     = sa0;
            *(uint4*)&An[lr * GSTR + ls + 4] = sa1;
            *(uint4*)&Bn[lr * GSTR + ls]     = sb0;
            *(uint4*)&Bn[lr * GSTR + ls + 4] = sb1;
        }
        __syncthreads();
        cur ^= 1;
    }

    float* Cp; const float* bp_; int ldc, cb;
    if (bn < CC) { Cp = C0; bp_ = bias0; ldc = CC;     cb = bn; }
    else         { Cp = C1; bp_ = bias1; ldc = 2 * CC; cb = bn - CC; }

    #pragma unroll
    for (int mi = 0; mi < 4; mi++) {
        int r0 = bm + wm + mi * 16 + g;
        #pragma unroll
        for (int ni = 0; ni < 4; ni++) {
            int c0 = cb + wn + ni * 8 + 2 * tg;
            float bx = bp_[c0], by = bp_[c0 + 1];
            *(float2*)&Cp[(size_t)r0 * ldc + c0] =
                make_float2(acc[mi][ni][0] + bx, acc[mi][ni][1] + by);
            *(float2*)&Cp[(size_t)(r0 + 8) * ldc + c0] =
                make_float2(acc[mi][ni][2] + bx, acc[mi][ni][3] + by);
        }
    }
}

// ================= Attention QK^T + softmax + attn scratch write =================
// 512 threads (16 warps). K streamed in 8 chunks of 128 m-rows, double-buffered:
// global loads for chunk c+1 overlap the mma on chunk c; one barrier per chunk.
#define QSTR 68
#define KSTR 68
#define SSTR 1044
#define AT_Q_WORDS  (32 * QSTR)
#define AT_K_WORDS  (2 * 128 * KSTR)
#define AT_S_WORDS  (32 * SSTR)
#define AT_SMEM ((AT_Q_WORDS + AT_K_WORDS + AT_S_WORDS) * 4)   // 211,968 B

__global__ __launch_bounds__(512) void mha_attn_qk(
    const float* __restrict__ gq, const float* __restrict__ gkv,
    float* __restrict__ gattn)
{
    extern __shared__ uint32_t sm_u[];
    uint32_t* Qs = sm_u;
    uint32_t* Ks = sm_u + AT_Q_WORDS;                 // [2][128*KSTR]
    float*    Sb = (float*)(sm_u + AT_Q_WORDS + AT_K_WORDS);

    const int t    = threadIdx.x;
    const int lane = t & 31;
    const int w    = t >> 5;         // 0..15
    const int g    = lane >> 2;
    const int tg   = lane & 3;
    const int nt   = blockIdx.x;
    const int h    = blockIdx.y;
    const int b    = blockIdx.z;
    const int n0   = nt * 32;

    // ---- load Q tile (32 x 64): one f4 per thread ----
    {
        int n  = t >> 4;
        int dq = (t & 15) << 2;
        float4 v = *(const float4*)(gq + (size_t)(b * NN + n0 + n) * CC + h * DH + dq);
        uint4 u;
        u.x = f2tf(v.x); u.y = f2tf(v.y); u.z = f2tf(v.z); u.w = f2tf(v.w);
        *(uint4*)&Qs[n * QSTR + dq] = u;
    }
    __syncthreads();

    // ---- Q fragments register-resident (n-half = w&1) ----
    uint32_t qa[8][4];
    {
        int r = (w & 1) * 16 + g;
        #pragma unroll
        for (int kd = 0; kd < 8; kd++) {
            int c = kd * 8 + tg;
            qa[kd][0] = Qs[r * QSTR + c];
            qa[kd][1] = Qs[(r + 8) * QSTR + c];
            qa[kd][2] = Qs[r * QSTR + c + 4];
            qa[kd][3] = Qs[(r + 8) * QSTR + c + 4];
        }
    }

    const float* kbase = gkv + (size_t)(b * NN) * (2 * CC) + h * DH;
    // per-thread K chunk-load indices: 2048 f4 slots -> 4 per thread
    const int krow[4] = { (0 * 512 + t) >> 4, (1 * 512 + t) >> 4,
                          (2 * 512 + t) >> 4, (3 * 512 + t) >> 4 };
    const int kdq = (t & 15) << 2;

    // preload chunk 0
    float4 kreg[4];
    #pragma unroll
    for (int i = 0; i < 4; i++)
        kreg[i] = *(const float4*)(kbase + (size_t)krow[i] * (2 * CC) + kdq);
    #pragma unroll
    for (int i = 0; i < 4; i++) {
        uint4 u;
        u.x = f2tf(kreg[i].x); u.y = f2tf(kreg[i].y); u.z = f2tf(kreg[i].z); u.w = f2tf(kreg[i].w);
        *(uint4*)&Ks[krow[i] * KSTR + kdq] = u;
    }
    __syncthreads();

    const int ms = (w >> 1) * 16;    // warp's 16-row m-slice within a 128 chunk

    for (int ch = 0; ch < 8; ch++) {
        const int cur = ch & 1;

        // issue global loads for next chunk (latency hidden under mma)
        if (ch < 7) {
            const int m1 = (ch + 1) * 128;
            #pragma unroll
            for (int i = 0; i < 4; i++)
                kreg[i] = *(const float4*)(kbase + (size_t)(m1 + krow[i]) * (2 * CC) + kdq);
        }

        // mma on current chunk
        const uint32_t* Kc = Ks + cur * (128 * KSTR);
        float acc[2][4];
        #pragma unroll
        for (int mt = 0; mt < 2; mt++)
            #pragma unroll
            for (int r = 0; r < 4; r++) acc[mt][r] = 0.0f;

        #pragma unroll
        for (int kd = 0; kd < 8; kd++) {
            uint32_t bf[2][2];
            const int c = kd * 8 + tg;
            #pragma unroll
            for (int mt = 0; mt < 2; mt++) {
                int r = ms + mt * 8 + g;
                bf[mt][0] = Kc[r * KSTR + c];
                bf[mt][1] = Kc[r * KSTR + c + 4];
            }
            #pragma unroll
            for (int mt = 0; mt < 2; mt++)
                MMA_TF32(acc[mt], qa[kd], bf[mt]);
        }

        {
            int row = (w & 1) * 16 + g;
            #pragma unroll
            for (int mt = 0; mt < 2; mt++) {
                int col = ch * 128 + ms + mt * 8 + 2 * tg;
                Sb[row * SSTR + col]           = acc[mt][0] * 0.125f;
                Sb[row * SSTR + col + 1]       = acc[mt][1] * 0.125f;
                Sb[(row + 8) * SSTR + col]     = acc[mt][2] * 0.125f;
                Sb[(row + 8) * SSTR + col + 1] = acc[mt][3] * 0.125f;
            }
        }

        // stage next chunk into the other buffer
        if (ch < 7) {
            uint32_t* Kn = Ks + (cur ^ 1) * (128 * KSTR);
            #pragma unroll
            for (int i = 0; i < 4; i++) {
                uint4 u;
                u.x = f2tf(kreg[i].x); u.y = f2tf(kreg[i].y);
                u.z = f2tf(kreg[i].z); u.w = f2tf(kreg[i].w);
                *(uint4*)&Kn[krow[i] * KSTR + kdq] = u;
            }
            __syncthreads();
        }
    }
    __syncthreads();

    // ---- softmax over m (each warp: 2 rows) ----
    {
        #pragma unroll
        for (int rr = 0; rr < 2; rr++) {
            float* row = Sb + (w * 2 + rr) * SSTR;
            float mx = -1e30f;
            for (int m = lane; m < 1024; m += 32) mx = fmaxf(mx, row[m]);
            #pragma unroll
            for (int o = 16; o; o >>= 1) mx = fmaxf(mx, __shfl_xor_sync(0xffffffffu, mx, o));
            float sum = 0.0f;
            for (int m = lane; m < 1024; m += 32) {
                float e = __expf(row[m] - mx);
                row[m] = e;
                sum += e;
            }
            #pragma unroll
            for (int o = 16; o; o >>= 1) sum += __shfl_xor_sync(0xffffffffu, sum, o);
            float inv = 1.0f / sum;
            for (int m = lane; m < 1024; m += 32) row[m] *= inv;
        }
    }
    __syncthreads();

    // ---- write attn scratch ([b,h,n,m], coalesced) ----
    {
        float* dst = gattn + ((size_t)((b * HH + h) * NN + n0)) * NN;
        #pragma unroll
        for (int r = 0; r < 16; r++) {
            int li  = r * 512 + t;
            int row = li >> 8;
            int mq  = (li & 255) << 2;
            float4 v = *(const float4*)(Sb + row * SSTR + mq);
            *(float4*)(dst + (size_t)row * NN + mq) = v;
        }
    }
}

// ================= PV batched GEMM: O = P @ V =================
#define PSTR  36
#define PVSTR 68
#define PV_SMEM ((2 * 128 * PSTR + 2 * 32 * PVSTR) * 4)   // 54,272 B

__global__ __launch_bounds__(512) void mha_pv(
    const float* __restrict__ gattn, const float* __restrict__ gkv,
    float* __restrict__ go)
{
    extern __shared__ uint32_t ps[];
    uint32_t* Asm = ps;
    uint32_t* Vsm = ps + 2 * 128 * PSTR;

    const int t    = threadIdx.x;
    const int lane = t & 31;
    const int w    = t >> 5;
    const int g    = lane >> 2;
    const int tg   = lane & 3;
    const int nt   = blockIdx.x;
    const int h    = blockIdx.y;
    const int b    = blockIdx.z;
    const int wn   = (w >> 2) * 32;
    const int wd   = (w & 3) * 16;

    const float* Pbase = gattn + ((size_t)((b * HH + h) * NN + nt * 128)) * NN;
    const float* Vbase = gkv + (size_t)(b * NN) * (2 * CC) + CC + h * DH;

    float acc[2][2][4];
    #pragma unroll
    for (int mi = 0; mi < 2; mi++)
        #pragma unroll
        for (int ni = 0; ni < 2; ni++)
            #pragma unroll
            for (int r = 0; r < 4; r++) acc[mi][ni][r] = 0.0f;

    float4 pa[2], pv;
    #pragma unroll
    for (int r = 0; r < 2; r++) {
        int li  = r * 512 + t;
        int row = li >> 3;
        int fq  = (li & 7) << 2;
        pa[r] = *(const float4*)(Pbase + (size_t)row * NN + fq);
    }
    {
        int row = t >> 4;
        int dq  = (t & 15) << 2;
        pv = *(const float4*)(Vbase + (size_t)row * (2 * CC) + dq);
    }
    #pragma unroll
    for (int r = 0; r < 2; r++) {
        int li  = r * 512 + t;
        int row = li >> 3;
        int fq  = (li & 7) << 2;
        uint4 u;
        u.x = f2tf(pa[r].x); u.y = f2tf(pa[r].y); u.z = f2tf(pa[r].z); u.w = f2tf(pa[r].w);
        *(uint4*)&Asm[row * PSTR + fq] = u;
    }
    {
        int row = t >> 4;
        int dq  = (t & 15) << 2;
        uint4 u;
        u.x = f2tf(pv.x); u.y = f2tf(pv.y); u.z = f2tf(pv.z); u.w = f2tf(pv.w);
        *(uint4*)&Vsm[row * PVSTR + dq] = u;
    }
    __syncthreads();

    int cur = 0;
    for (int k0 = 32; k0 <= 1024; k0 += 32) {
        const bool more = (k0 < 1024);
        if (more) {
            #pragma unroll
            for (int r = 0; r < 2; r++) {
                int li  = r * 512 + t;
                int row = li >> 3;
                int fq  = (li & 7) << 2;
                pa[r] = *(const float4*)(Pbase + (size_t)row * NN + k0 + fq);
            }
            {
                int row = t >> 4;
                int dq  = (t & 15) << 2;
                pv = *(const float4*)(Vbase + (size_t)(k0 + row) * (2 * CC) + dq);
            }
        }

        const uint32_t* Ac = Asm + cur * (128 * PSTR);
        const uint32_t* Vc = Vsm + cur * (32 * PVSTR);
        #pragma unroll
        for (int kk = 0; kk < 32; kk += 8) {
            uint32_t af[2][4], bf[2][2];
            const int c = kk + tg;
            #pragma unroll
            for (int mi = 0; mi < 2; mi++) {
                int r = wn + mi * 16 + g;
                af[mi][0] = Ac[r * PSTR + c];
                af[mi][1] = Ac[(r + 8) * PSTR + c];
                af[mi][2] = Ac[r * PSTR + c + 4];
                af[mi][3] = Ac[(r + 8) * PSTR + c + 4];
            }
            #pragma unroll
            for (int ni = 0; ni < 2; ni++) {
                int vc = wd + ni * 8 + g;
                bf[ni][0] = Vc[c * PVSTR + vc];
                bf[ni][1] = Vc[(c + 4) * PVSTR + vc];
            }
            #pragma unroll
            for (int mi = 0; mi < 2; mi++)
                #pragma unroll
                for (int ni = 0; ni < 2; ni++)
                    MMA_TF32(acc[mi][ni], af[mi], bf[ni]);
        }

        if (more) {
            uint32_t* An = Asm + (cur ^ 1) * (128 * PSTR);
            uint32_t* Vn = Vsm + (cur ^ 1) * (32 * PVSTR);
            #pragma unroll
            for (int r = 0; r < 2; r++) {
                int li  = r * 512 + t;
                int row = li >> 3;
                int fq  = (li & 7) << 2;
                uint4 u;
                u.x = f2tf(pa[r].x); u.y = f2tf(pa[r].y); u.z = f2tf(pa[r].z); u.w = f2tf(pa[r].w);
                *(uint4*)&An[row * PSTR + fq] = u;
            }
            {
                int row = t >> 4;
                int dq  = (t & 15) << 2;
                uint4 u;
                u.x = f2tf(pv.x); u.y = f2tf(pv.y); u.z = f2tf(pv.z); u.w = f2tf(pv.w);
                *(uint4*)&Vn[row * PVSTR + dq] = u;
            }
        }
        __syncthreads();
        cur ^= 1;
    }

    #pragma unroll
    for (int mi = 0; mi < 2; mi++) {
        int r0 = b * NN + nt * 128 + wn + mi * 16 + g;
        #pragma unroll
        for (int ni = 0; ni < 2; ni++) {
            int c0 = h * DH + wd + ni * 8 + 2 * tg;
            *(float2*)&go[(size_t)r0 * CC + c0] =
                make_float2(acc[mi][ni][0], acc[mi][ni][1]);
            *(float2*)&go[(size_t)(r0 + 8) * CC + c0] =
                make_float2(acc[mi][ni][2], acc[mi][ni][3]);
        }
    }
}

// ---------------- launch ----------------
extern "C" void kernel_launch(void* const* d_in, const int* in_sizes, int n_in,
                              void* d_out, int out_size)
{
    const float* x   = (const float*)d_in[0];
    const float* Wq  = (const float*)d_in[1];
    const float* bq  = (const float*)d_in[2];
    const float* Wkv = (const float*)d_in[3];
    const float* bkv = (const float*)d_in[4];
    const float* Wp  = (const float*)d_in[5];
    const float* bp  = (const float*)d_in[6];

    float* out      = (float*)d_out;
    float* attn_out = out + (size_t)OUT_ELEMS;

    float* q = nullptr; float* kv = nullptr; float* o = nullptr; float* attn = nullptr;
    cudaGetSymbolAddress((void**)&q,    g_mha_q);
    cudaGetSymbolAddress((void**)&kv,   g_mha_kv);
    cudaGetSymbolAddress((void**)&o,    g_mha_o);
    cudaGetSymbolAddress((void**)&attn, g_mha_attn);

    cudaFuncSetAttribute(mha_attn_qk,
                         cudaFuncAttributeMaxDynamicSharedMemorySize, AT_SMEM);
    cudaFuncSetAttribute(mha_pv,
                         cudaFuncAttributeMaxDynamicSharedMemorySize, PV_SMEM);

    const bool has_attn_out = out_size >= (int)(OUT_ELEMS + ATTN_ELEMS);

    // Fused: Q = x@Wq^T+bq and KV = x@Wkv^T+bkv (384 GEMM CTAs, ncol=24)
    mha_gemm_fused<<<384, 256>>>(
        x, Wq, Wkv, bq, bkv, q, kv, CC, 24, 384, nullptr, nullptr);
    // QK^T + softmax -> attn scratch [b,h,n,m]
    mha_attn_qk<<<dim3(NN / 32, HH, BB), 512, AT_SMEM>>>(q, kv, attn);
    // O = P @ V
    mha_pv<<<dim3(NN / 128, HH, BB), 512, PV_SMEM>>>(attn, kv, o);
    // out = O @ Wp^T + bp  (+ transpose attn -> [b,n,m,h] co-scheduled)
    {
        int tblocks = has_attn_out ? (4 * NN * BB) : 0;   // 8192
        mha_gemm_fused<<<128 + tblocks, 256>>>(
            o, Wp, nullptr, bp, nullptr, out, nullptr, CC, 8, 128,
            attn, attn_out);
    }
}

// round 16
// speedup vs baseline: 1.3262x; 1.3262x over previous
#include <cuda_runtime.h>
#include <cuda_fp16.h>
#include <cstdint>
#include <cstddef>

// Problem constants
#define BB   2
#define NN   1024
#define CC   1024
#define HH   16
#define DH   64
#define MROWS (BB*NN)
#define OUT_ELEMS  (BB*NN*CC)                 // 2,097,152
#define ATTN_ELEMS (BB*NN*NN*HH)              // 33,554,432

// ---------------- scratch ----------------
__device__ float g_mha_q[MROWS * CC];
__device__ float g_mha_kv[MROWS * 2 * CC];
__device__ float g_mha_o[MROWS * CC];
__device__ float g_mha_attn[ATTN_ELEMS];      // [b,h,n,m]

// ---------------- fp16 helpers ----------------
__device__ __forceinline__ uint32_t f2h2(float lo, float hi) {
    __half2 h = __floats2half2_rn(lo, hi);
    return *reinterpret_cast<uint32_t*>(&h);
}

// m16n8k16 fp16 mma, fp32 accumulate.
// A (row-major): 4 regs; a0=(row g, k 2tg..+1), a1=(g+8), a2=(g, k 2tg+8..+9), a3=(g+8,+8)
// B (col-major): 2 regs; b0=(col g, k 2tg..+1), b1=(col g, k 2tg+8..+9)
#define MMA_F16(d, a, b) \
    asm volatile("mma.sync.aligned.m16n8k16.row.col.f32.f16.f16.f32 " \
        "{%0,%1,%2,%3}, {%4,%5,%6,%7}, {%8,%9}, {%0,%1,%2,%3};" \
        : "+f"((d)[0]), "+f"((d)[1]), "+f"((d)[2]), "+f"((d)[3]) \
        : "r"((a)[0]), "r"((a)[1]), "r"((a)[2]), "r"((a)[3]), \
          "r"((b)[0]), "r"((b)[1]))

// ================= GEMM: C = A @ B^T + bias, split-output =================
// 128x128 block, 256 threads (8 warps 2m x 4n), warp 64x32, k-tile 32 floats
// (= 16 half2 words/row, 2 mma k16 steps), double-buffered smem.
#define GSTR 20                      // 16 words + 4 pad -> conflict-free frags
#define GHALF (128 * GSTR)

__global__ __launch_bounds__(256) void mha_gemm8(
    const float* __restrict__ A,
    const float* __restrict__ B0, const float* __restrict__ B1,
    const float* __restrict__ bias0, const float* __restrict__ bias1,
    float* __restrict__ C0, float* __restrict__ C1, int K)
{
    __shared__ uint32_t Asm[2 * GHALF];
    __shared__ uint32_t Bsm[2 * GHALF];

    const int t    = threadIdx.x;
    const int lane = t & 31;
    const int w    = t >> 5;
    const int bm   = blockIdx.y * 128;
    const int bn   = blockIdx.x * 128;
    const int wm   = (w >> 2) * 64;
    const int wn   = (w & 3) * 32;
    const int g    = lane >> 2;
    const int tg   = lane & 3;

    const int lr = t >> 1;           // row 0..127
    const int lf = (t & 1) * 16;     // float offset 0 or 16
    const int lw = (t & 1) * 8;      // word offset 0 or 8

    float acc[4][4][4];
    #pragma unroll
    for (int mi = 0; mi < 4; mi++)
        #pragma unroll
        for (int ni = 0; ni < 4; ni++)
            #pragma unroll
            for (int r = 0; r < 4; r++) acc[mi][ni][r] = 0.0f;

    const float* Ap = A + (size_t)(bm + lr) * K + lf;
    const float* Bp;
    {
        int cn = bn + lr;
        Bp = ((cn < CC) ? (B0 + (size_t)cn * K)
                        : (B1 + (size_t)(cn - CC) * K)) + lf;
    }

    float4 la[4], lb[4];
    #pragma unroll
    for (int q = 0; q < 4; q++) {
        la[q] = *(const float4*)(Ap + q * 4);
        lb[q] = *(const float4*)(Bp + q * 4);
    }

    // store chunk 0
    {
        uint4 ua0, ua1, ub0, ub1;
        ua0.x = f2h2(la[0].x, la[0].y); ua0.y = f2h2(la[0].z, la[0].w);
        ua0.z = f2h2(la[1].x, la[1].y); ua0.w = f2h2(la[1].z, la[1].w);
        ua1.x = f2h2(la[2].x, la[2].y); ua1.y = f2h2(la[2].z, la[2].w);
        ua1.z = f2h2(la[3].x, la[3].y); ua1.w = f2h2(la[3].z, la[3].w);
        ub0.x = f2h2(lb[0].x, lb[0].y); ub0.y = f2h2(lb[0].z, lb[0].w);
        ub0.z = f2h2(lb[1].x, lb[1].y); ub0.w = f2h2(lb[1].z, lb[1].w);
        ub1.x = f2h2(lb[2].x, lb[2].y); ub1.y = f2h2(lb[2].z, lb[2].w);
        ub1.z = f2h2(lb[3].x, lb[3].y); ub1.w = f2h2(lb[3].z, lb[3].w);
        *(uint4*)&Asm[lr * GSTR + lw]     = ua0;
        *(uint4*)&Asm[lr * GSTR + lw + 4] = ua1;
        *(uint4*)&Bsm[lr * GSTR + lw]     = ub0;
        *(uint4*)&Bsm[lr * GSTR + lw + 4] = ub1;
    }
    __syncthreads();

    int cur = 0;
    for (int k0 = 32; k0 <= K; k0 += 32) {
        const bool more = (k0 < K);
        if (more) {
            #pragma unroll
            for (int q = 0; q < 4; q++) {
                la[q] = *(const float4*)(Ap + k0 + q * 4);
                lb[q] = *(const float4*)(Bp + k0 + q * 4);
            }
        }

        const uint32_t* Ac = Asm + cur * GHALF;
        const uint32_t* Bc = Bsm + cur * GHALF;
        #pragma unroll
        for (int s = 0; s < 2; s++) {
            uint32_t af[4][4], bf[4][2];
            const int c = s * 8 + tg;
            #pragma unroll
            for (int mi = 0; mi < 4; mi++) {
                int r = wm + mi * 16 + g;
                af[mi][0] = Ac[r * GSTR + c];
                af[mi][1] = Ac[(r + 8) * GSTR + c];
                af[mi][2] = Ac[r * GSTR + c + 4];
                af[mi][3] = Ac[(r + 8) * GSTR + c + 4];
            }
            #pragma unroll
            for (int ni = 0; ni < 4; ni++) {
                int r = wn + ni * 8 + g;
                bf[ni][0] = Bc[r * GSTR + c];
                bf[ni][1] = Bc[r * GSTR + c + 4];
            }
            #pragma unroll
            for (int mi = 0; mi < 4; mi++)
                #pragma unroll
                for (int ni = 0; ni < 4; ni++)
                    MMA_F16(acc[mi][ni], af[mi], bf[ni]);
        }

        if (more) {
            uint32_t* An = Asm + (cur ^ 1) * GHALF;
            uint32_t* Bn = Bsm + (cur ^ 1) * GHALF;
            uint4 ua0, ua1, ub0, ub1;
            ua0.x = f2h2(la[0].x, la[0].y); ua0.y = f2h2(la[0].z, la[0].w);
            ua0.z = f2h2(la[1].x, la[1].y); ua0.w = f2h2(la[1].z, la[1].w);
            ua1.x = f2h2(la[2].x, la[2].y); ua1.y = f2h2(la[2].z, la[2].w);
            ua1.z = f2h2(la[3].x, la[3].y); ua1.w = f2h2(la[3].z, la[3].w);
            ub0.x = f2h2(lb[0].x, lb[0].y); ub0.y = f2h2(lb[0].z, lb[0].w);
            ub0.z = f2h2(lb[1].x, lb[1].y); ub0.w = f2h2(lb[1].z, lb[1].w);
            ub1.x = f2h2(lb[2].x, lb[2].y); ub1.y = f2h2(lb[2].z, lb[2].w);
            ub1.z = f2h2(lb[3].x, lb[3].y); ub1.w = f2h2(lb[3].z, lb[3].w);
            *(uint4*)&An[lr * GSTR + lw]     = ua0;
            *(uint4*)&An[lr * GSTR + lw + 4] = ua1;
            *(uint4*)&Bn[lr * GSTR + lw]     = ub0;
            *(uint4*)&Bn[lr * GSTR + lw + 4] = ub1;
        }
        __syncthreads();
        cur ^= 1;
    }

    float* Cp; const float* bp_; int ldc, cb;
    if (bn < CC) { Cp = C0; bp_ = bias0; ldc = CC;     cb = bn; }
    else         { Cp = C1; bp_ = bias1; ldc = 2 * CC; cb = bn - CC; }

    #pragma unroll
    for (int mi = 0; mi < 4; mi++) {
        int r0 = bm + wm + mi * 16 + g;
        #pragma unroll
        for (int ni = 0; ni < 4; ni++) {
            int c0 = cb + wn + ni * 8 + 2 * tg;
            float bx = bp_[c0], by = bp_[c0 + 1];
            *(float2*)&Cp[(size_t)r0 * ldc + c0] =
                make_float2(acc[mi][ni][0] + bx, acc[mi][ni][1] + by);
            *(float2*)&Cp[(size_t)(r0 + 8) * ldc + c0] =
                make_float2(acc[mi][ni][2] + bx, acc[mi][ni][3] + by);
        }
    }
}

// ================= Attention QK^T + softmax + attn scratch write =================
// 512 threads (16 warps). d=64 -> 32 half2 words/row. 4 chunks of 256 m-rows.
#define QSTR 36
#define KSTR 36
#define SSTR 1044
#define AT_Q_WORDS  (32 * QSTR)
#define AT_K_WORDS  (256 * KSTR)
#define AT_S_WORDS  (32 * SSTR)
#define AT_SMEM ((AT_Q_WORDS + AT_K_WORDS + AT_S_WORDS) * 4)   // 175,104 B

__global__ __launch_bounds__(512) void mha_attn_qk(
    const float* __restrict__ gq, const float* __restrict__ gkv,
    float* __restrict__ gattn)
{
    extern __shared__ uint32_t sm_u[];
    uint32_t* Qs = sm_u;
    uint32_t* Ks = sm_u + AT_Q_WORDS;
    float*    Sb = (float*)(sm_u + AT_Q_WORDS + AT_K_WORDS);

    const int t    = threadIdx.x;
    const int lane = t & 31;
    const int w    = t >> 5;         // 0..15
    const int g    = lane >> 2;
    const int tg   = lane & 3;
    const int nt   = blockIdx.x;
    const int h    = blockIdx.y;
    const int b    = blockIdx.z;
    const int n0   = nt * 32;

    // ---- load Q tile (32 x 64 floats -> 32 x 32 words), one f4 per thread ----
    {
        int n  = t >> 4;
        int fq = (t & 15) << 2;
        float4 v = *(const float4*)(gq + (size_t)(b * NN + n0 + n) * CC + h * DH + fq);
        uint2 u;
        u.x = f2h2(v.x, v.y);
        u.y = f2h2(v.z, v.w);
        *(uint2*)&Qs[n * QSTR + (fq >> 1)] = u;
    }
    __syncthreads();

    // ---- Q fragments register-resident (n-half = w&1); 4 k16 steps over d ----
    uint32_t qa[4][4];
    {
        int r = (w & 1) * 16 + g;
        #pragma unroll
        for (int kd = 0; kd < 4; kd++) {
            int c = kd * 8 + tg;
            qa[kd][0] = Qs[r * QSTR + c];
            qa[kd][1] = Qs[(r + 8) * QSTR + c];
            qa[kd][2] = Qs[r * QSTR + c + 4];
            qa[kd][3] = Qs[(r + 8) * QSTR + c + 4];
        }
    }

    const float* kbase = gkv + (size_t)(b * NN) * (2 * CC) + h * DH;

    for (int ch = 0; ch < 4; ch++) {
        const int m0 = ch * 256;
        __syncthreads();
        #pragma unroll
        for (int r = 0; r < 8; r++) {
            int li  = r * 512 + t;               // 4096 f4 slots: 256 rows x 16 f4
            int row = li >> 4;
            int fq  = (li & 15) << 2;
            float4 v = *(const float4*)(kbase + (size_t)(m0 + row) * (2 * CC) + fq);
            uint2 u;
            u.x = f2h2(v.x, v.y);
            u.y = f2h2(v.z, v.w);
            *(uint2*)&Ks[row * KSTR + (fq >> 1)] = u;
        }
        __syncthreads();

        float acc[4][4];
        #pragma unroll
        for (int mt = 0; mt < 4; mt++)
            #pragma unroll
            for (int r = 0; r < 4; r++) acc[mt][r] = 0.0f;

        const int ms = (w >> 1) * 32;            // warp's 32-m slice in chunk
        #pragma unroll
        for (int kd = 0; kd < 4; kd++) {
            uint32_t bf[4][2];
            const int c = kd * 8 + tg;
            #pragma unroll
            for (int mt = 0; mt < 4; mt++) {
                int r = ms + mt * 8 + g;
                bf[mt][0] = Ks[r * KSTR + c];
                bf[mt][1] = Ks[r * KSTR + c + 4];
            }
            #pragma unroll
            for (int mt = 0; mt < 4; mt++)
                MMA_F16(acc[mt], qa[kd], bf[mt]);
        }

        int row = (w & 1) * 16 + g;
        #pragma unroll
        for (int mt = 0; mt < 4; mt++) {
            int col = m0 + ms + mt * 8 + 2 * tg;
            Sb[row * SSTR + col]           = acc[mt][0] * 0.125f;
            Sb[row * SSTR + col + 1]       = acc[mt][1] * 0.125f;
            Sb[(row + 8) * SSTR + col]     = acc[mt][2] * 0.125f;
            Sb[(row + 8) * SSTR + col + 1] = acc[mt][3] * 0.125f;
        }
    }
    __syncthreads();

    // ---- softmax over m (each warp: 2 rows) ----
    {
        #pragma unroll
        for (int rr = 0; rr < 2; rr++) {
            float* row = Sb + (w * 2 + rr) * SSTR;
            float mx = -1e30f;
            for (int m = lane; m < 1024; m += 32) mx = fmaxf(mx, row[m]);
            #pragma unroll
            for (int o = 16; o; o >>= 1) mx = fmaxf(mx, __shfl_xor_sync(0xffffffffu, mx, o));
            float sum = 0.0f;
            for (int m = lane; m < 1024; m += 32) {
                float e = __expf(row[m] - mx);
                row[m] = e;
                sum += e;
            }
            #pragma unroll
            for (int o = 16; o; o >>= 1) sum += __shfl_xor_sync(0xffffffffu, sum, o);
            float inv = 1.0f / sum;
            for (int m = lane; m < 1024; m += 32) row[m] *= inv;
        }
    }
    __syncthreads();

    // ---- write attn scratch ([b,h,n,m], coalesced) ----
    {
        float* dst = gattn + ((size_t)((b * HH + h) * NN + n0)) * NN;
        #pragma unroll
        for (int r = 0; r < 16; r++) {
            int li  = r * 512 + t;
            int row = li >> 8;
            int mq  = (li & 255) << 2;
            float4 v = *(const float4*)(Sb + row * SSTR + mq);
            *(float4*)(dst + (size_t)row * NN + mq) = v;
        }
    }
}

// ================= PV batched GEMM: O = P @ V =================
// Block: (n-tile 128, h, b). 512 thr, 16 warps (4n x 4d), warp 32x16.
// k-chunk 32 (16 half2 k-pairs). V stored k-pair-major: word[kp][d] = {V[2kp][d], V[2kp+1][d]}.
#define PSTR  20
#define PVSTR 72
#define PV_A_WORDS (2 * 128 * PSTR)
#define PV_V_WORDS (2 * 16 * PVSTR)
#define PV_SMEM ((PV_A_WORDS + PV_V_WORDS) * 4)   // 29,696 B

__global__ __launch_bounds__(512) void mha_pv(
    const float* __restrict__ gattn, const float* __restrict__ gkv,
    float* __restrict__ go)
{
    extern __shared__ uint32_t ps[];
    uint32_t* Asm = ps;                      // [2][128*PSTR]
    uint32_t* Vsm = ps + PV_A_WORDS;         // [2][16*PVSTR]

    const int t    = threadIdx.x;
    const int lane = t & 31;
    const int w    = t >> 5;
    const int g    = lane >> 2;
    const int tg   = lane & 3;
    const int nt   = blockIdx.x;
    const int h    = blockIdx.y;
    const int b    = blockIdx.z;
    const int wn   = (w >> 2) * 32;
    const int wd   = (w & 3) * 16;

    const float* Pbase = gattn + ((size_t)((b * HH + h) * NN + nt * 128)) * NN;
    const float* Vbase = gkv + (size_t)(b * NN) * (2 * CC) + CC + h * DH;

    float acc[2][2][4];
    #pragma unroll
    for (int mi = 0; mi < 2; mi++)
        #pragma unroll
        for (int ni = 0; ni < 2; ni++)
            #pragma unroll
            for (int r = 0; r < 4; r++) acc[mi][ni][r] = 0.0f;

    // staging regs
    float4 pa[2];
    float  va[2][2];

    // preload chunk 0
    #pragma unroll
    for (int i = 0; i < 2; i++) {
        int li  = i * 512 + t;                // 1024 f4 slots: 128 rows x 8 f4
        int row = li >> 3;
        int fq  = (li & 7) << 2;
        pa[i] = *(const float4*)(Pbase + (size_t)row * NN + fq);
    }
    #pragma unroll
    for (int i = 0; i < 2; i++) {
        int s  = i * 512 + t;                 // 1024 word slots: 16 kp x 64 d
        int kp = s >> 6;
        int d  = s & 63;
        va[i][0] = Vbase[(size_t)(2 * kp)     * (2 * CC) + d];
        va[i][1] = Vbase[(size_t)(2 * kp + 1) * (2 * CC) + d];
    }
    #pragma unroll
    for (int i = 0; i < 2; i++) {
        int li  = i * 512 + t;
        int row = li >> 3;
        int fq  = (li & 7) << 2;
        uint2 u;
        u.x = f2h2(pa[i].x, pa[i].y);
        u.y = f2h2(pa[i].z, pa[i].w);
        *(uint2*)&Asm[row * PSTR + (fq >> 1)] = u;
    }
    #pragma unroll
    for (int i = 0; i < 2; i++) {
        int s  = i * 512 + t;
        int kp = s >> 6;
        int d  = s & 63;
        Vsm[kp * PVSTR + d] = f2h2(va[i][0], va[i][1]);
    }
    __syncthreads();

    int cur = 0;
    for (int k0 = 32; k0 <= 1024; k0 += 32) {
        const bool more = (k0 < 1024);
        if (more) {
            #pragma unroll
            for (int i = 0; i < 2; i++) {
                int li  = i * 512 + t;
                int row = li >> 3;
                int fq  = (li & 7) << 2;
                pa[i] = *(const float4*)(Pbase + (size_t)row * NN + k0 + fq);
            }
            #pragma unroll
            for (int i = 0; i < 2; i++) {
                int s  = i * 512 + t;
                int kp = s >> 6;
                int d  = s & 63;
                va[i][0] = Vbase[(size_t)(k0 + 2 * kp)     * (2 * CC) + d];
                va[i][1] = Vbase[(size_t)(k0 + 2 * kp + 1) * (2 * CC) + d];
            }
        }

        const uint32_t* Ac = Asm + cur * (128 * PSTR);
        const uint32_t* Vc = Vsm + cur * (16 * PVSTR);
        #pragma unroll
        for (int s = 0; s < 2; s++) {
            uint32_t af[2][4], bf[2][2];
            const int c = s * 8 + tg;
            #pragma unroll
            for (int mi = 0; mi < 2; mi++) {
                int r = wn + mi * 16 + g;
                af[mi][0] = Ac[r * PSTR + c];
                af[mi][1] = Ac[(r + 8) * PSTR + c];
                af[mi][2] = Ac[r * PSTR + c + 4];
                af[mi][3] = Ac[(r + 8) * PSTR + c + 4];
            }
            #pragma unroll
            for (int ni = 0; ni < 2; ni++) {
                int vc = wd + ni * 8 + g;
                int kp = s * 8 + tg;
                bf[ni][0] = Vc[kp * PVSTR + vc];
                bf[ni][1] = Vc[(kp + 4) * PVSTR + vc];
            }
            #pragma unroll
            for (int mi = 0; mi < 2; mi++)
                #pragma unroll
                for (int ni = 0; ni < 2; ni++)
                    MMA_F16(acc[mi][ni], af[mi], bf[ni]);
        }

        if (more) {
            uint32_t* An = Asm + (cur ^ 1) * (128 * PSTR);
            uint32_t* Vn = Vsm + (cur ^ 1) * (16 * PVSTR);
            #pragma unroll
            for (int i = 0; i < 2; i++) {
                int li  = i * 512 + t;
                int row = li >> 3;
                int fq  = (li & 7) << 2;
                uint2 u;
                u.x = f2h2(pa[i].x, pa[i].y);
                u.y = f2h2(pa[i].z, pa[i].w);
                *(uint2*)&An[row * PSTR + (fq >> 1)] = u;
            }
            #pragma unroll
            for (int i = 0; i < 2; i++) {
                int s  = i * 512 + t;
                int kp = s >> 6;
                int d  = s & 63;
                Vn[kp * PVSTR + d] = f2h2(va[i][0], va[i][1]);
            }
        }
        __syncthreads();
        cur ^= 1;
    }

    #pragma unroll
    for (int mi = 0; mi < 2; mi++) {
        int r0 = b * NN + nt * 128 + wn + mi * 16 + g;
        #pragma unroll
        for (int ni = 0; ni < 2; ni++) {
            int c0 = h * DH + wd + ni * 8 + 2 * tg;
            *(float2*)&go[(size_t)r0 * CC + c0] =
                make_float2(acc[mi][ni][0], acc[mi][ni][1]);
            *(float2*)&go[(size_t)(r0 + 8) * CC + c0] =
                make_float2(acc[mi][ni][2], acc[mi][ni][3]);
        }
    }
}

// ---------------- transpose attn: [b,h,n,m] -> [b,n,m,h] ----------------
__global__ __launch_bounds__(256) void mha_transpose_attn(
    const float* __restrict__ src, float* __restrict__ dst)
{
    __shared__ float tile[16][257];
    const int t  = threadIdx.x;
    const int mc = blockIdx.x;
    const int n  = blockIdx.y;
    const int b  = blockIdx.z;
    const int m0 = mc * 256;

    #pragma unroll
    for (int r = 0; r < 4; r++) {
        int li = r * 256 + t;
        int hh = li >> 6;
        int mq = (li & 63) << 2;
        float4 v = *(const float4*)(src + ((size_t)((b * HH + hh) * NN + n)) * NN + m0 + mq);
        tile[hh][mq]     = v.x;
        tile[hh][mq + 1] = v.y;
        tile[hh][mq + 2] = v.z;
        tile[hh][mq + 3] = v.w;
    }
    __syncthreads();

    float* dbase = dst + ((size_t)(b * NN + n) * NN + m0) * HH;
    #pragma unroll
    for (int r = 0; r < 4; r++) {
        int li = r * 256 + t;
        int m  = li >> 2;
        int hq = (li & 3) << 2;
        float4 v;
        v.x = tile[hq + 0][m];
        v.y = tile[hq + 1][m];
        v.z = tile[hq + 2][m];
        v.w = tile[hq + 3][m];
        *(float4*)(dbase + (size_t)m * HH + hq) = v;
    }
}

// ---------------- launch ----------------
extern "C" void kernel_launch(void* const* d_in, const int* in_sizes, int n_in,
                              void* d_out, int out_size)
{
    const float* x   = (const float*)d_in[0];
    const float* Wq  = (const float*)d_in[1];
    const float* bq  = (const float*)d_in[2];
    const float* Wkv = (const float*)d_in[3];
    const float* bkv = (const float*)d_in[4];
    const float* Wp  = (const float*)d_in[5];
    const float* bp  = (const float*)d_in[6];

    float* out      = (float*)d_out;
    float* attn_out = out + (size_t)OUT_ELEMS;

    float* q = nullptr; float* kv = nullptr; float* o = nullptr; float* attn = nullptr;
    cudaGetSymbolAddress((void**)&q,    g_mha_q);
    cudaGetSymbolAddress((void**)&kv,   g_mha_kv);
    cudaGetSymbolAddress((void**)&o,    g_mha_o);
    cudaGetSymbolAddress((void**)&attn, g_mha_attn);

    cudaFuncSetAttribute(mha_attn_qk,
                         cudaFuncAttributeMaxDynamicSharedMemorySize, AT_SMEM);
    cudaFuncSetAttribute(mha_pv,
                         cudaFuncAttributeMaxDynamicSharedMemorySize, PV_SMEM);

    // Fused: Q = x@Wq^T+bq and KV = x@Wkv^T+bkv
    mha_gemm8<<<dim3(3 * CC / 128, MROWS / 128), 256>>>(
        x, Wq, Wkv, bq, bkv, q, kv, CC);
    // QK^T + softmax -> attn scratch [b,h,n,m]
    mha_attn_qk<<<dim3(NN / 32, HH, BB), 512, AT_SMEM>>>(q, kv, attn);
    // O = P @ V
    mha_pv<<<dim3(NN / 128, HH, BB), 512, PV_SMEM>>>(attn, kv, o);
    // out = O @ Wp^T + bp
    mha_gemm8<<<dim3(CC / 128, MROWS / 128), 256>>>(
        o, Wp, nullptr, bp, nullptr, out, nullptr, CC);
    // attn -> [b,n,m,h]
    if (out_size >= (int)(OUT_ELEMS + ATTN_ELEMS)) {
        mha_transpose_attn<<<dim3(NN / 256, NN, BB), 256>>>(attn, attn_out);
    }
}